// round 5
// baseline (speedup 1.0000x reference)
#include <cuda_runtime.h>
#include <cuda_bf16.h>
#include <cstdint>

// ---------------- problem constants ----------------
#define NROW 8192
#define KDIM 64
#define NAUG 72
#define NTILES 9                 // 72 / 8
#define TILE_M 128
#define KC 32                    // K per chunk (2 x k16 fragments)
#define SPLITS 8
#define KSPLIT (NROW / SPLITS)   // 1024
#define NCHUNK (KSPLIT / KC)     // 32
#define NTHREADS 128
#define MTILES (NROW / TILE_M)   // 64
#define NGCHUNK (NROW / KC)      // 256 global k-chunks
#define BCH_BYTES (2 * NTILES * 256)   // 4608 bytes per B chunk
#define NPART (MTILES * SPLITS)  // 512

// ---------------- device scratch ----------------
__device__ float g_sq[NROW];
__device__ __align__(16) unsigned char g_yaugB[NGCHUNK * BCH_BYTES];  // 1.18 MB, fragment-packed bf16
__device__ float g_part[NPART];
__device__ unsigned int g_cnt = 0;

// ---------------- helpers ----------------
__device__ __forceinline__ uint32_t pack_bf16x2(float lo, float hi) {
    uint32_t r;
    asm("cvt.rn.bf16x2.f32 %0, %1, %2;" : "=r"(r) : "f"(hi), "f"(lo));
    return r;
}
__device__ __forceinline__ void mma_bf16(float* c, const uint32_t* a, uint32_t b0, uint32_t b1) {
    asm volatile(
        "mma.sync.aligned.m16n8k16.row.col.f32.bf16.bf16.f32 "
        "{%0,%1,%2,%3},{%4,%5,%6,%7},{%8,%9},{%0,%1,%2,%3};"
        : "+f"(c[0]), "+f"(c[1]), "+f"(c[2]), "+f"(c[3])
        : "r"(a[0]), "r"(a[1]), "r"(a[2]), "r"(a[3]), "r"(b0), "r"(b1));
}

// byte offset of element (kg, n) inside g_yaugB (fragment-register layout)
__device__ __forceinline__ uint32_t b_offset(int kg, int n) {
    int gc  = kg >> 5;            // global chunk
    int k16 = (kg >> 4) & 1;      // k16 fragment within chunk
    int kl  = kg & 15;            // k within fragment
    int nt  = n >> 3;
    int n8  = n & 7;
    int lane = n8 * 4 + ((kl & 7) >> 1);
    return (uint32_t)(((gc * 2 + k16) * NTILES + nt) * 256 + lane * 8
                      + ((kl >> 3) & 1) * 4 + (kl & 1) * 2);
}

// ---------------- prep: sq + fragment-packed bf16 Yaug ----------------
__global__ void prep(const float* __restrict__ Y) {
    int w    = (blockIdx.x * blockDim.x + threadIdx.x) >> 5;
    int lane = threadIdx.x & 31;
    if (w >= NROW) return;
    if (w == 0 && lane == 0) g_cnt = 0;

    const float* yr = Y + (size_t)w * KDIM;
    float v0 = yr[lane], v1 = yr[lane + 32];
    float s = v0 * v0 + v1 * v1;
#pragma unroll
    for (int o = 16; o; o >>= 1) s += __shfl_xor_sync(0xffffffffu, s, o);
    if (lane == 0) g_sq[w] = s;

    *reinterpret_cast<__nv_bfloat16*>(g_yaugB + b_offset(w, lane))      = __float2bfloat16_rn(v0);
    *reinterpret_cast<__nv_bfloat16*>(g_yaugB + b_offset(w, lane + 32)) = __float2bfloat16_rn(v1);
    if (lane < 8) {
        float v = (lane == 0) ? 1.0f : (lane == 1) ? s : 0.0f;
        *reinterpret_cast<__nv_bfloat16*>(g_yaugB + b_offset(w, 64 + lane)) = __float2bfloat16_rn(v);
    }
}

// ---------------- main kernel: barrier-free register-pipelined streaming ----------------
__global__ __launch_bounds__(NTHREADS, 3)
void spectral_main(const float* __restrict__ W, const float* __restrict__ Y,
                   float* __restrict__ out) {
    const int tid  = threadIdx.x;
    const int wid  = tid >> 5;
    const int lane = tid & 31;
    const int g    = lane >> 2;
    const int tg   = lane & 3;
    const int m0   = blockIdx.x * TILE_M;
    const int kbase = blockIdx.y * KSPLIT;

    float acc[2][NTILES][4];
#pragma unroll
    for (int mf = 0; mf < 2; ++mf)
#pragma unroll
        for (int nt = 0; nt < NTILES; ++nt)
#pragma unroll
            for (int q = 0; q < 4; ++q) acc[mf][nt][q] = 0.0f;

    // per-thread W base: row m0 + wid*32 + g, col kbase + tg*2
    const float* wp = W + (size_t)(m0 + wid * 32 + g) * NROW + kbase + tg * 2;
    // B base for this k-split
    const unsigned char* bsplit = g_yaugB + (size_t)(kbase >> 5) * BCH_BYTES;

    // af[r][c]: r in {0..3} -> rows +{0,8,16,24}; c in {0..3} -> cols +{0,8,16,24}
    float2 af[4][4];
#pragma unroll
    for (int r = 0; r < 4; ++r)
#pragma unroll
        for (int c = 0; c < 4; ++c)
            af[r][c] = __ldcs(reinterpret_cast<const float2*>(wp + r * 8 * NROW + c * 8));

    for (int t = 0; t < NCHUNK; ++t) {
        // Convert current chunk fragments fp32 -> bf16x2.
        // ab[ks][mf][j]: ks=c>>1, half=c&1; mf=r>>1, rh=r&1; j=half*2+rh
        uint32_t ab[2][2][4];
#pragma unroll
        for (int r = 0; r < 4; ++r)
#pragma unroll
            for (int c = 0; c < 4; ++c)
                ab[c >> 1][r >> 1][(c & 1) * 2 + (r & 1)] = pack_bf16x2(af[r][c].x, af[r][c].y);

        // Prefetch next chunk's W fragments (guard the final iteration)
        {
            const int nt_ = (t + 1 < NCHUNK) ? (t + 1) : 0;
            const float* np = wp + nt_ * KC;
#pragma unroll
            for (int r = 0; r < 4; ++r)
#pragma unroll
                for (int c = 0; c < 4; ++c)
                    af[r][c] = __ldcs(reinterpret_cast<const float2*>(np + r * 8 * NROW + c * 8));
        }

        // B fragments for this chunk (L1-resident, warp-coalesced 256B rows)
        const unsigned char* bch = bsplit + (size_t)t * BCH_BYTES;
#pragma unroll
        for (int ks = 0; ks < 2; ++ks) {
            uint2 b[NTILES];
#pragma unroll
            for (int nt = 0; nt < NTILES; ++nt)
                b[nt] = __ldg(reinterpret_cast<const uint2*>(
                    bch + (ks * NTILES + nt) * 256 + lane * 8));
#pragma unroll
            for (int nt = 0; nt < NTILES; ++nt) {
                mma_bf16(acc[0][nt], ab[ks][0], b[nt].x, b[nt].y);
                mma_bf16(acc[1][nt], ab[ks][1], b[nt].x, b[nt].y);
            }
        }
    }

    // ---- epilogue: contract Z fragments against coefficients ----
    float partial = 0.0f;
#pragma unroll
    for (int mf = 0; mf < 2; ++mf) {
#pragma unroll
        for (int half = 0; half < 2; ++half) {
            int i = m0 + wid * 32 + mf * 16 + half * 8 + g;
            const float* yr = Y + (size_t)i * KDIM;
            float s = 0.0f;
#pragma unroll
            for (int nt = 0; nt < 8; ++nt) {
                int col = nt * 8 + tg * 2;
                s = fmaf(yr[col],     acc[mf][nt][half * 2 + 0], s);
                s = fmaf(yr[col + 1], acc[mf][nt][half * 2 + 1], s);
            }
            float e = -2.0f * s;
            if (tg == 0) {
                e = fmaf(g_sq[i], acc[mf][8][half * 2 + 0], e);
                e += acc[mf][8][half * 2 + 1];
            }
            partial += e;
        }
    }
#pragma unroll
    for (int o = 16; o; o >>= 1) partial += __shfl_xor_sync(0xffffffffu, partial, o);

    __shared__ float red[8];
    __shared__ int flag;
    if (lane == 0) red[wid] = partial;
    __syncthreads();

    // ---- last-block deterministic final reduction ----
    if (tid == 0) {
        g_part[blockIdx.y * MTILES + blockIdx.x] = red[0] + red[1] + red[2] + red[3];
        __threadfence();
        unsigned int old = atomicAdd(&g_cnt, 1u);
        flag = (old == NPART - 1) ? 1 : 0;
    }
    __syncthreads();
    if (flag) {
        __threadfence();
        float s = g_part[tid] + g_part[tid + 128] + g_part[tid + 256] + g_part[tid + 384];
#pragma unroll
        for (int o = 16; o; o >>= 1) s += __shfl_xor_sync(0xffffffffu, s, o);
        if (lane == 0) red[wid] = s;
        __syncthreads();
        if (tid == 0) {
            out[0] = (red[0] + red[1] + red[2] + red[3]) * (1.0f / (2.0f * (float)NROW));
            g_cnt = 0;
        }
    }
}

// ---------------- launch ----------------
extern "C" void kernel_launch(void* const* d_in, const int* in_sizes, int n_in,
                              void* d_out, int out_size) {
    const float* W;
    const float* Y;
    if (in_sizes[0] == NROW * NROW) {
        W = (const float*)d_in[0];
        Y = (const float*)d_in[1];
    } else {
        Y = (const float*)d_in[0];
        W = (const float*)d_in[1];
    }
    prep<<<NROW / 8, 256>>>(Y);
    spectral_main<<<dim3(MTILES, SPLITS), NTHREADS>>>(W, Y, (float*)d_out);
}